// round 11
// baseline (speedup 1.0000x reference)
#include <cuda_runtime.h>
#include <cuda_fp16.h>
#include <cstdint>

// GatedFusion via mma.sync f16 (m16n8k16, fp32 accum).
// R11 = R7 skeleton (64x64 warp tiles, 4 warps/CTA, LDG->compute->STS->sync)
// with BK=64 / 2-stage: half the tile iterations & barriers, 16 LDG.128 in
// flight per thread, compute block (~2048cyc) covers staging latency.
// Live math (softmax over singleton axis == 1 -> word/topk branch dead):
//   gate  = sigmoid([time|text] @ gate_w^T + gate_b)   (M=16384, N=896, K=1792)
//   fused = gate*time + (1-gate)*text
//   out   = fused @ out_w^T + out_b                    (M=16384, N=896, K=896)

#define M_TOT 16384
#define D_DIM 896
#define K1    1792

#define BM 128
#define BN 128
#define BK 64
#define THREADS 128
#define STAGES 2
#define AB_OFF (STAGES * 1024)                // uint4 entries: B region offset
#define SMEM_BYTES (2 * STAGES * 1024 * 16)   // 64 KB -> 2 CTAs/SM

static __device__ __half g_tf_h[(size_t)M_TOT * D_DIM];
static __device__ __half g_xf_h[(size_t)M_TOT * D_DIM];
static __device__ __half g_gw_h[(size_t)D_DIM * K1];
static __device__ __half g_ow_h[(size_t)D_DIM * D_DIM];
static __device__ __half g_fused[(size_t)M_TOT * D_DIM];

// ---------------- small helpers ---------------------------------------------
__device__ __forceinline__ void ldm_x4(uint32_t* r, uint32_t addr) {
    asm volatile("ldmatrix.sync.aligned.m8n8.x4.shared.b16 {%0,%1,%2,%3}, [%4];"
                 : "=r"(r[0]), "=r"(r[1]), "=r"(r[2]), "=r"(r[3]) : "r"(addr));
}
__device__ __forceinline__ void mma_f16(float* c, const uint32_t* a, const uint32_t* b) {
    asm volatile(
        "mma.sync.aligned.m16n8k16.row.col.f32.f16.f16.f32 "
        "{%0,%1,%2,%3}, {%4,%5,%6,%7}, {%8,%9}, {%0,%1,%2,%3};"
        : "+f"(c[0]), "+f"(c[1]), "+f"(c[2]), "+f"(c[3])
        : "r"(a[0]), "r"(a[1]), "r"(a[2]), "r"(a[3]), "r"(b[0]), "r"(b[1]));
}

// ---------------- fused fp32 -> fp16 pre-convert (one launch) ----------------
#define N_ACT ((size_t)M_TOT * D_DIM)
#define N_GW  ((size_t)D_DIM * K1)
#define N_OW  ((size_t)D_DIM * D_DIM)
__global__ void k_f2h_all(const float* __restrict__ tf, const float* __restrict__ xf,
                          const float* __restrict__ gw, const float* __restrict__ ow) {
    const size_t tot = (2 * N_ACT + N_GW + N_OW) / 4;
    for (size_t g = blockIdx.x * blockDim.x + threadIdx.x; g < tot;
         g += (size_t)gridDim.x * blockDim.x) {
        const float* src; __half* dst; size_t i = g * 4;
        if (i < N_ACT) {
            src = tf + i; dst = g_tf_h + i;
        } else if (i < 2 * N_ACT) {
            src = xf + (i - N_ACT); dst = g_xf_h + (i - N_ACT);
        } else if (i < 2 * N_ACT + N_GW) {
            src = gw + (i - 2 * N_ACT); dst = g_gw_h + (i - 2 * N_ACT);
        } else {
            src = ow + (i - 2 * N_ACT - N_GW); dst = g_ow_h + (i - 2 * N_ACT - N_GW);
        }
        float4 v = *reinterpret_cast<const float4*>(src);
        __half2 hh[2] = {__floats2half2_rn(v.x, v.y), __floats2half2_rn(v.z, v.w)};
        *reinterpret_cast<uint2*>(dst) = *reinterpret_cast<const uint2*>(hh);
    }
}

// ---------------- staging: LDG.128 -> regs -> swizzled STS.128 ---------------
// Tile = 128 rows x 64 k (half) for A and B. 16B entries, 8 k8-slabs:
//   entry(slab,row) = slab*128 + (row ^ ((slab&3)*2))
// 128 threads: row32 = tid>>2 (0..31), slabL = tid&3; u<4 rows, h<2 slab half.
__device__ __forceinline__ void ldg_pair(uint4 (&ra)[8], uint4 (&rb)[8],
                                         const __half* __restrict__ A, int ldA,
                                         int m0, int kA,
                                         const __half* __restrict__ B, int ldB,
                                         int n0, int kB, int row32, int slabL) {
#pragma unroll
    for (int u = 0; u < 4; u++) {
#pragma unroll
        for (int h = 0; h < 2; h++) {
            const int row = row32 + u * 32;
            const int slab = slabL + h * 4;
            ra[u * 2 + h] = *reinterpret_cast<const uint4*>(&A[(size_t)(m0 + row) * ldA + kA + slab * 8]);
            rb[u * 2 + h] = *reinterpret_cast<const uint4*>(&B[(size_t)(n0 + row) * ldB + kB + slab * 8]);
        }
    }
}
__device__ __forceinline__ void sts_pair(uint4* sm, int stage, const uint4 (&ra)[8],
                                         const uint4 (&rb)[8], int row32, int slabL) {
#pragma unroll
    for (int u = 0; u < 4; u++) {
#pragma unroll
        for (int h = 0; h < 2; h++) {
            const int row = row32 + u * 32;
            const int slab = slabL + h * 4;
            const int e = stage * 1024 + slab * 128 + (row ^ ((slab & 3) * 2));
            sm[e] = ra[u * 2 + h];
            sm[AB_OFF + e] = rb[u * 2 + h];
        }
    }
}

// ---------------- compute: warp tile 64x64, mi=4 x ni=8, 4 k16 steps ---------
#define GEMM_COMPUTE(cur)                                                         \
    _Pragma("unroll")                                                             \
    for (int ks = 0; ks < 4; ks++) {                                              \
        uint32_t af[4][4], bf[8][2];                                              \
        _Pragma("unroll")                                                         \
        for (int mi = 0; mi < 4; mi++) {                                          \
            const int slab = ks * 2 + a_kh;                                       \
            const int row = wm * 64 + mi * 16 + a_row;                            \
            ldm_x4(af[mi], sbase +                                                \
                   (uint32_t)((cur) * 1024 + slab * 128 + (row ^ ((slab & 3) * 2))) * 16); \
        }                                                                         \
        _Pragma("unroll")                                                         \
        for (int np = 0; np < 4; np++) {                                          \
            const int slab = ks * 2 + b_kh;                                       \
            const int nrow = wn * 64 + np * 16 + b_row;                           \
            uint32_t t[4];                                                        \
            ldm_x4(t, sbase + (uint32_t)AB_OFF * 16 +                             \
                   (uint32_t)((cur) * 1024 + slab * 128 + (nrow ^ ((slab & 3) * 2))) * 16); \
            bf[np * 2][0] = t[0]; bf[np * 2][1] = t[1];                           \
            bf[np * 2 + 1][0] = t[2]; bf[np * 2 + 1][1] = t[3];                   \
        }                                                                         \
        _Pragma("unroll")                                                         \
        for (int mi = 0; mi < 4; mi++)                                            \
            _Pragma("unroll")                                                     \
            for (int ni = 0; ni < 8; ni++)                                        \
                mma_f16(acc[mi][ni], af[mi], bf[ni]);                             \
    }

#define GEMM_PREAMBLE                                                             \
    extern __shared__ uint4 smem_dyn[];                                           \
    const uint32_t sbase = (uint32_t)__cvta_generic_to_shared(smem_dyn);          \
    const int tid  = threadIdx.x;                                                 \
    const int wid  = tid >> 5;                                                    \
    const int lane = tid & 31;                                                    \
    const int qrow = lane >> 2;                                                   \
    const int qk   = lane & 3;                                                    \
    const int wm   = wid & 1;                                                     \
    const int wn   = wid >> 1;                                                    \
    const int m0   = blockIdx.y * BM;                                             \
    const int n0   = blockIdx.x * BN;                                             \
    const int row32 = tid >> 2;                                                   \
    const int slabL = tid & 3;                                                    \
    const int a_row = lane & 15;                                                  \
    const int a_kh  = lane >> 4;                                                  \
    const int b_row = (lane & 7) + ((lane >> 4) << 3);                            \
    const int b_kh  = (lane >> 3) & 1;                                            \
    float acc[4][8][4];                                                           \
    _Pragma("unroll")                                                             \
    for (int mi = 0; mi < 4; mi++)                                                \
        _Pragma("unroll")                                                         \
        for (int ni = 0; ni < 8; ni++)                                            \
            _Pragma("unroll")                                                     \
            for (int t = 0; t < 4; t++) acc[mi][ni][t] = 0.f;

// 2-stage, one sync per BK=64 tile (R1/R7 ordering):
//   iter kt: LDG(kt+1) -> compute(kt, slot kt&1) -> STS(kt+1, slot ~kt&1) -> sync
// STS targets the slot whose last reader was compute(kt-1), ordered by the
// previous sync; the sync publishes STS(kt+1) before compute(kt+1).
#define GEMM_MAINLOOP(NT, SRC_A, LD_A, K_A, SRC_B, LD_B)                          \
    {                                                                             \
        uint4 ra[8], rb[8];                                                       \
        ldg_pair(ra, rb, SRC_A(0), LD_A, m0, K_A(0), SRC_B, LD_B, n0, 0, row32, slabL); \
        sts_pair(smem_dyn, 0, ra, rb, row32, slabL);                              \
        __syncthreads();                                                          \
        for (int kt = 0; kt < (NT); kt++) {                                       \
            if (kt + 1 < (NT)) {                                                  \
                const int kb = (kt + 1) * BK;                                     \
                ldg_pair(ra, rb, SRC_A(kb), LD_A, m0, K_A(kb), SRC_B, LD_B, n0, kb, row32, slabL); \
            }                                                                     \
            GEMM_COMPUTE(kt & 1)                                                  \
            if (kt + 1 < (NT)) sts_pair(smem_dyn, (kt + 1) & 1, ra, rb, row32, slabL); \
            __syncthreads();                                                      \
        }                                                                         \
    }

// ============================================================================
// Kernel 1: gate GEMM (K=1792, A = [time|text] concat) + sigmoid/blend fuse
// ============================================================================
#define GATE_SRC(kb) ((kb) < D_DIM ? g_tf_h : g_xf_h)
#define GATE_K(kb)   ((kb) < D_DIM ? (kb) : (kb) - D_DIM)
#define ID_SRC(kb)   (g_fused)
#define ID_K(kb)     (kb)

__global__ void __launch_bounds__(THREADS, 2)
k_gate_fuse(const float* __restrict__ tf, const float* __restrict__ xf,
            const float* __restrict__ gb)
{
    GEMM_PREAMBLE
    GEMM_MAINLOOP(K1 / BK, GATE_SRC, D_DIM, GATE_K, g_gw_h, K1)

    // epilogue: z = acc + gb; g = sigmoid(z); fused = g*tf + (1-g)*xf (fp32 blend)
#pragma unroll
    for (int mi = 0; mi < 4; mi++) {
#pragma unroll
        for (int half = 0; half < 2; half++) {
            const int m = m0 + wm * 64 + mi * 16 + qrow + half * 8;
            const float* trow = tf + (size_t)m * D_DIM;
            const float* xrow = xf + (size_t)m * D_DIM;
            __half* frow = g_fused + (size_t)m * D_DIM;
#pragma unroll
            for (int ni = 0; ni < 8; ni++) {
                const int n = n0 + wn * 64 + ni * 8 + 2 * qk;
                const float c0 = acc[mi][ni][half * 2 + 0];
                const float c1 = acc[mi][ni][half * 2 + 1];
                const float2 gbv = *reinterpret_cast<const float2*>(&gb[n]);
                const float2 tv  = *reinterpret_cast<const float2*>(&trow[n]);
                const float2 xv  = *reinterpret_cast<const float2*>(&xrow[n]);
                const float g0 = 1.f / (1.f + __expf(-(c0 + gbv.x)));
                const float g1 = 1.f / (1.f + __expf(-(c1 + gbv.y)));
                const float f0 = g0 * tv.x + (1.f - g0) * xv.x;
                const float f1 = g1 * tv.y + (1.f - g1) * xv.y;
                *reinterpret_cast<__half2*>(&frow[n]) = __floats2half2_rn(f0, f1);
            }
        }
    }
}

// ============================================================================
// Kernel 2: out = fused @ out_w^T + out_b   (K=896)
// ============================================================================
__global__ void __launch_bounds__(THREADS, 2)
k_out_proj(const float* __restrict__ ob, float* __restrict__ out)
{
    GEMM_PREAMBLE
    GEMM_MAINLOOP(D_DIM / BK, ID_SRC, D_DIM, ID_K, g_ow_h, D_DIM)

#pragma unroll
    for (int mi = 0; mi < 4; mi++) {
#pragma unroll
        for (int half = 0; half < 2; half++) {
            const int m = m0 + wm * 64 + mi * 16 + qrow + half * 8;
            float* orow = out + (size_t)m * D_DIM;
#pragma unroll
            for (int ni = 0; ni < 8; ni++) {
                const int n = n0 + wn * 64 + ni * 8 + 2 * qk;
                const float2 obv = *reinterpret_cast<const float2*>(&ob[n]);
                float2 o;
                o.x = acc[mi][ni][half * 2 + 0] + obv.x;
                o.y = acc[mi][ni][half * 2 + 1] + obv.y;
                *reinterpret_cast<float2*>(&orow[n]) = o;
            }
        }
    }
}

extern "C" void kernel_launch(void* const* d_in, const int* in_sizes, int n_in,
                              void* d_out, int out_size) {
    const float* tf = (const float*)d_in[0];   // time_feat [16,1024,896]
    const float* xf = (const float*)d_in[1];   // text_feat [16,1024,896]
    // d_in[2] = word (dead: softmax over singleton axis == 1)
    const float* gw = (const float*)d_in[3];   // gate_w [896, 1792]
    const float* gb = (const float*)d_in[4];   // gate_b [896]
    const float* ow = (const float*)d_in[5];   // out_w  [896, 896]
    const float* ob = (const float*)d_in[6];   // out_b  [896]
    float* out = (float*)d_out;                // [16,1024,896] fp32

    static bool attr_set = false;
    if (!attr_set) {
        cudaFuncSetAttribute(k_gate_fuse, cudaFuncAttributeMaxDynamicSharedMemorySize, SMEM_BYTES);
        cudaFuncSetAttribute(k_out_proj, cudaFuncAttributeMaxDynamicSharedMemorySize, SMEM_BYTES);
        attr_set = true;
    }

    k_f2h_all<<<2368, 256>>>(tf, xf, gw, ow);

    dim3 grid(D_DIM / BN, M_TOT / BM);  // (7, 128)
    k_gate_fuse<<<grid, THREADS, SMEM_BYTES>>>(tf, xf, gb);
    k_out_proj<<<grid, THREADS, SMEM_BYTES>>>(ob, out);
}

// round 12
// speedup vs baseline: 1.0275x; 1.0275x over previous
#include <cuda_runtime.h>
#include <cuda_fp16.h>
#include <cstdint>

// GatedFusion via mma.sync f16 (m16n8k16, fp32 accum).
// R12 = R7 skeleton (318us champion: 64x64 warp tiles, 4 warps/CTA, 3-stage
// smem, LDG->compute->STS->sync) with activation fp32->fp16 conversion FUSED
// into gate staging; only weights are pre-converted (~3us vs 30us).
// Evidence says the legacy-HMMA pipe is ~95% bound (R5/R7 plateau across
// pipeline shapes), so the extra LDG issue hides under the tensor block.
// Live math (softmax over singleton axis == 1 -> word/topk branch dead):
//   gate  = sigmoid([time|text] @ gate_w^T + gate_b)   (M=16384, N=896, K=1792)
//   fused = gate*time + (1-gate)*text
//   out   = fused @ out_w^T + out_b                    (M=16384, N=896, K=896)

#define M_TOT 16384
#define D_DIM 896
#define K1    1792

#define BM 128
#define BN 128
#define BK 32
#define THREADS 128
#define STAGES 3
#define AB_OFF (STAGES * 512)                 // uint4 entries: B region offset
#define SMEM_BYTES (2 * STAGES * 512 * 16)    // 48 KB -> 2 CTAs/SM

static __device__ __half g_gw_h[(size_t)D_DIM * K1];
static __device__ __half g_ow_h[(size_t)D_DIM * D_DIM];
static __device__ __half g_fused[(size_t)M_TOT * D_DIM];

// ---------------- small helpers ---------------------------------------------
__device__ __forceinline__ void ldm_x4(uint32_t* r, uint32_t addr) {
    asm volatile("ldmatrix.sync.aligned.m8n8.x4.shared.b16 {%0,%1,%2,%3}, [%4];"
                 : "=r"(r[0]), "=r"(r[1]), "=r"(r[2]), "=r"(r[3]) : "r"(addr));
}
__device__ __forceinline__ void mma_f16(float* c, const uint32_t* a, const uint32_t* b) {
    asm volatile(
        "mma.sync.aligned.m16n8k16.row.col.f32.f16.f16.f32 "
        "{%0,%1,%2,%3}, {%4,%5,%6,%7}, {%8,%9}, {%0,%1,%2,%3};"
        : "+f"(c[0]), "+f"(c[1]), "+f"(c[2]), "+f"(c[3])
        : "r"(a[0]), "r"(a[1]), "r"(a[2]), "r"(a[3]), "r"(b[0]), "r"(b[1]));
}
__device__ __forceinline__ uint4 f32x8_to_h8(float4 v0, float4 v1) {
    __half2 h0 = __floats2half2_rn(v0.x, v0.y);
    __half2 h1 = __floats2half2_rn(v0.z, v0.w);
    __half2 h2 = __floats2half2_rn(v1.x, v1.y);
    __half2 h3 = __floats2half2_rn(v1.z, v1.w);
    uint4 r;
    r.x = *reinterpret_cast<uint32_t*>(&h0);
    r.y = *reinterpret_cast<uint32_t*>(&h1);
    r.z = *reinterpret_cast<uint32_t*>(&h2);
    r.w = *reinterpret_cast<uint32_t*>(&h3);
    return r;
}

// ---------------- weights-only fp32 -> fp16 pre-convert ----------------------
#define N_GW  ((size_t)D_DIM * K1)
#define N_OW  ((size_t)D_DIM * D_DIM)
__global__ void k_f2h_w(const float* __restrict__ gw, const float* __restrict__ ow) {
    const size_t tot = (N_GW + N_OW) / 4;
    for (size_t g = blockIdx.x * blockDim.x + threadIdx.x; g < tot;
         g += (size_t)gridDim.x * blockDim.x) {
        const float* src; __half* dst; size_t i = g * 4;
        if (i < N_GW) { src = gw + i; dst = g_gw_h + i; }
        else          { src = ow + (i - N_GW); dst = g_ow_h + (i - N_GW); }
        float4 v = *reinterpret_cast<const float4*>(src);
        __half2 hh[2] = {__floats2half2_rn(v.x, v.y), __floats2half2_rn(v.z, v.w)};
        *reinterpret_cast<uint2*>(dst) = *reinterpret_cast<const uint2*>(hh);
    }
}

// ---------------- staging ----------------------------------------------------
// Tile = 128 rows x 32 k (half) for A and B. 16B entries:
//   entry(slab,row) = slab*128 + (row ^ (slab*2)), slab = k8/8 in {0..3}
// 128 threads: row32 = tid>>2 (0..31), slab = tid&3; u<4 covers 128 rows.

// half A + half B (out_proj path; identical to R7)
__device__ __forceinline__ void ldg_pair_hh(uint4 (&ra)[4], uint4 (&rb)[4],
                                            const __half* __restrict__ A, int ldA,
                                            int m0, int kA,
                                            const __half* __restrict__ B, int ldB,
                                            int n0, int kB, int row32, int slab) {
#pragma unroll
    for (int u = 0; u < 4; u++) {
        const int row = row32 + u * 32;
        ra[u] = *reinterpret_cast<const uint4*>(&A[(size_t)(m0 + row) * ldA + kA + slab * 8]);
        rb[u] = *reinterpret_cast<const uint4*>(&B[(size_t)(n0 + row) * ldB + kB + slab * 8]);
    }
}
// fp32 A (convert in flight) + half B (gate path)
__device__ __forceinline__ void ldg_pair_fh(uint4 (&ra)[4], uint4 (&rb)[4],
                                            const float* __restrict__ A, int ldA,
                                            int m0, int kA,
                                            const __half* __restrict__ B, int ldB,
                                            int n0, int kB, int row32, int slab) {
#pragma unroll
    for (int u = 0; u < 4; u++) {
        const int row = row32 + u * 32;
        const float* ap = &A[(size_t)(m0 + row) * ldA + kA + slab * 8];
        float4 v0 = *reinterpret_cast<const float4*>(ap);
        float4 v1 = *reinterpret_cast<const float4*>(ap + 4);
        ra[u] = f32x8_to_h8(v0, v1);
        rb[u] = *reinterpret_cast<const uint4*>(&B[(size_t)(n0 + row) * ldB + kB + slab * 8]);
    }
}
__device__ __forceinline__ void sts_pair(uint4* sm, int stage, const uint4 (&ra)[4],
                                         const uint4 (&rb)[4], int row32, int slab) {
#pragma unroll
    for (int u = 0; u < 4; u++) {
        const int row = row32 + u * 32;
        const int e = stage * 512 + slab * 128 + (row ^ (slab * 2));
        sm[e] = ra[u];
        sm[AB_OFF + e] = rb[u];
    }
}

// ---------------- compute: warp tile 64x64, mi=4 x ni=8, m16n8k16 ------------
#define GEMM_COMPUTE(cur)                                                         \
    _Pragma("unroll")                                                             \
    for (int ks = 0; ks < 2; ks++) {                                              \
        uint32_t af[4][4], bf[8][2];                                              \
        _Pragma("unroll")                                                         \
        for (int mi = 0; mi < 4; mi++) {                                          \
            const int slab = ks * 2 + a_kh;                                       \
            const int row = wm * 64 + mi * 16 + a_row;                            \
            ldm_x4(af[mi], sbase +                                                \
                   (uint32_t)((cur) * 512 + slab * 128 + (row ^ (slab * 2))) * 16); \
        }                                                                         \
        _Pragma("unroll")                                                         \
        for (int np = 0; np < 4; np++) {                                          \
            const int slab = ks * 2 + b_kh;                                       \
            const int nrow = wn * 64 + np * 16 + b_row;                           \
            uint32_t t[4];                                                        \
            ldm_x4(t, sbase + (uint32_t)AB_OFF * 16 +                             \
                   (uint32_t)((cur) * 512 + slab * 128 + (nrow ^ (slab * 2))) * 16); \
            bf[np * 2][0] = t[0]; bf[np * 2][1] = t[1];                           \
            bf[np * 2 + 1][0] = t[2]; bf[np * 2 + 1][1] = t[3];                   \
        }                                                                         \
        _Pragma("unroll")                                                         \
        for (int mi = 0; mi < 4; mi++)                                            \
            _Pragma("unroll")                                                     \
            for (int ni = 0; ni < 8; ni++)                                        \
                mma_f16(acc[mi][ni], af[mi], bf[ni]);                             \
    }

#define GEMM_PREAMBLE                                                             \
    extern __shared__ uint4 smem_dyn[];                                           \
    const uint32_t sbase = (uint32_t)__cvta_generic_to_shared(smem_dyn);          \
    const int tid  = threadIdx.x;                                                 \
    const int wid  = tid >> 5;                                                    \
    const int lane = tid & 31;                                                    \
    const int qrow = lane >> 2;                                                   \
    const int qk   = lane & 3;                                                    \
    const int wm   = wid & 1;                                                     \
    const int wn   = wid >> 1;                                                    \
    const int m0   = blockIdx.y * BM;                                             \
    const int n0   = blockIdx.x * BN;                                             \
    const int row32 = tid >> 2;                                                   \
    const int slabL = tid & 3;                                                    \
    const int a_row = lane & 15;                                                  \
    const int a_kh  = lane >> 4;                                                  \
    const int b_row = (lane & 7) + ((lane >> 4) << 3);                            \
    const int b_kh  = (lane >> 3) & 1;                                            \
    float acc[4][8][4];                                                           \
    _Pragma("unroll")                                                             \
    for (int mi = 0; mi < 4; mi++)                                                \
        _Pragma("unroll")                                                         \
        for (int ni = 0; ni < 8; ni++)                                            \
            _Pragma("unroll")                                                     \
            for (int t = 0; t < 4; t++) acc[mi][ni][t] = 0.f;

// R7 pipeline: 3-stage, one sync per tile.
//   iter kt: LDG(kt+2) -> compute(kt, slot kt%3) -> STS(kt+2 into (kt+2)%3 ==
//   (kt-1)%3, whose compute finished before the previous sync) -> sync.
#define GEMM_MAINLOOP(NT, LDG_CALL, LDG_CALL0, LDG_CALL1)                         \
    {                                                                             \
        uint4 ra[4], rb[4];                                                       \
        LDG_CALL0;                                                                \
        sts_pair(smem_dyn, 0, ra, rb, row32, slabL);                              \
        LDG_CALL1;                                                                \
        sts_pair(smem_dyn, 1, ra, rb, row32, slabL);                              \
        __syncthreads();                                                          \
        for (int kt = 0; kt < (NT); kt++) {                                       \
            const int kn = kt + 2;                                                \
            if (kn < (NT)) {                                                      \
                const int kb = kn * BK;                                           \
                LDG_CALL;                                                         \
            }                                                                     \
            GEMM_COMPUTE(kt % STAGES)                                             \
            if (kn < (NT)) sts_pair(smem_dyn, kn % STAGES, ra, rb, row32, slabL); \
            __syncthreads();                                                      \
        }                                                                         \
    }

// ============================================================================
// Kernel 1: gate GEMM (K=1792, A = [time|text] fp32 concat, cvt in staging)
// ============================================================================
__global__ void __launch_bounds__(THREADS, 2)
k_gate_fuse(const float* __restrict__ tf, const float* __restrict__ xf,
            const float* __restrict__ gb)
{
    GEMM_PREAMBLE
    GEMM_MAINLOOP(K1 / BK,
        ldg_pair_fh(ra, rb, (kb < D_DIM) ? tf : xf, D_DIM, m0,
                    (kb < D_DIM) ? kb : kb - D_DIM, g_gw_h, K1, n0, kb, row32, slabL),
        ldg_pair_fh(ra, rb, tf, D_DIM, m0, 0, g_gw_h, K1, n0, 0, row32, slabL),
        ldg_pair_fh(ra, rb, tf, D_DIM, m0, BK, g_gw_h, K1, n0, BK, row32, slabL))

    // epilogue: z = acc + gb; g = sigmoid(z); fused = g*tf + (1-g)*xf (fp32 blend)
#pragma unroll
    for (int mi = 0; mi < 4; mi++) {
#pragma unroll
        for (int half = 0; half < 2; half++) {
            const int m = m0 + wm * 64 + mi * 16 + qrow + half * 8;
            const float* trow = tf + (size_t)m * D_DIM;
            const float* xrow = xf + (size_t)m * D_DIM;
            __half* frow = g_fused + (size_t)m * D_DIM;
#pragma unroll
            for (int ni = 0; ni < 8; ni++) {
                const int n = n0 + wn * 64 + ni * 8 + 2 * qk;
                const float c0 = acc[mi][ni][half * 2 + 0];
                const float c1 = acc[mi][ni][half * 2 + 1];
                const float2 gbv = *reinterpret_cast<const float2*>(&gb[n]);
                const float2 tv  = *reinterpret_cast<const float2*>(&trow[n]);
                const float2 xv  = *reinterpret_cast<const float2*>(&xrow[n]);
                const float g0 = 1.f / (1.f + __expf(-(c0 + gbv.x)));
                const float g1 = 1.f / (1.f + __expf(-(c1 + gbv.y)));
                const float f0 = g0 * tv.x + (1.f - g0) * xv.x;
                const float f1 = g1 * tv.y + (1.f - g1) * xv.y;
                *reinterpret_cast<__half2*>(&frow[n]) = __floats2half2_rn(f0, f1);
            }
        }
    }
}

// ============================================================================
// Kernel 2: out = fused @ out_w^T + out_b   (K=896, all-half staging)
// ============================================================================
__global__ void __launch_bounds__(THREADS, 2)
k_out_proj(const float* __restrict__ ob, float* __restrict__ out)
{
    GEMM_PREAMBLE
    GEMM_MAINLOOP(D_DIM / BK,
        ldg_pair_hh(ra, rb, g_fused, D_DIM, m0, kb, g_ow_h, D_DIM, n0, kb, row32, slabL),
        ldg_pair_hh(ra, rb, g_fused, D_DIM, m0, 0, g_ow_h, D_DIM, n0, 0, row32, slabL),
        ldg_pair_hh(ra, rb, g_fused, D_DIM, m0, BK, g_ow_h, D_DIM, n0, BK, row32, slabL))

#pragma unroll
    for (int mi = 0; mi < 4; mi++) {
#pragma unroll
        for (int half = 0; half < 2; half++) {
            const int m = m0 + wm * 64 + mi * 16 + qrow + half * 8;
            float* orow = out + (size_t)m * D_DIM;
#pragma unroll
            for (int ni = 0; ni < 8; ni++) {
                const int n = n0 + wn * 64 + ni * 8 + 2 * qk;
                const float2 obv = *reinterpret_cast<const float2*>(&ob[n]);
                float2 o;
                o.x = acc[mi][ni][half * 2 + 0] + obv.x;
                o.y = acc[mi][ni][half * 2 + 1] + obv.y;
                *reinterpret_cast<float2*>(&orow[n]) = o;
            }
        }
    }
}

extern "C" void kernel_launch(void* const* d_in, const int* in_sizes, int n_in,
                              void* d_out, int out_size) {
    const float* tf = (const float*)d_in[0];   // time_feat [16,1024,896]
    const float* xf = (const float*)d_in[1];   // text_feat [16,1024,896]
    // d_in[2] = word (dead: softmax over singleton axis == 1)
    const float* gw = (const float*)d_in[3];   // gate_w [896, 1792]
    const float* gb = (const float*)d_in[4];   // gate_b [896]
    const float* ow = (const float*)d_in[5];   // out_w  [896, 896]
    const float* ob = (const float*)d_in[6];   // out_b  [896]
    float* out = (float*)d_out;                // [16,1024,896] fp32

    static bool attr_set = false;
    if (!attr_set) {
        cudaFuncSetAttribute(k_gate_fuse, cudaFuncAttributeMaxDynamicSharedMemorySize, SMEM_BYTES);
        cudaFuncSetAttribute(k_out_proj, cudaFuncAttributeMaxDynamicSharedMemorySize, SMEM_BYTES);
        attr_set = true;
    }

    k_f2h_w<<<592, 256>>>(gw, ow);   // weights only: ~2.4M elems, ~3us

    dim3 grid(D_DIM / BN, M_TOT / BM);  // (7, 128)
    k_gate_fuse<<<grid, THREADS, SMEM_BYTES>>>(tf, xf, gb);
    k_out_proj<<<grid, THREADS, SMEM_BYTES>>>(ob, out);
}

// round 13
// speedup vs baseline: 1.6993x; 1.6538x over previous
#include <cuda_runtime.h>
#include <cuda_fp16.h>
#include <cstdint>

// GatedFusion via mma.sync f16 (m16n8k16, fp32 accum).
// R13 = R7 champion skeleton byte-for-byte (64x64 warp tiles, 4 warps/CTA,
// 3-stage smem, LDG->compute->STS->one-sync, all-fp16 mainloop staging),
// with ONE change: gate epilogue blends from the half activation copies
// (g_tf_h/g_xf_h) instead of fp32 tf/xf — halves epilogue DRAM traffic.
// Mainloop is jointly l1tex/tensor-saturated (R8/R9/R11/R12 all regressed);
// do not add bytes or registers to it.
// Live math (softmax over singleton axis == 1 -> word/topk branch dead):
//   gate  = sigmoid([time|text] @ gate_w^T + gate_b)   (M=16384, N=896, K=1792)
//   fused = gate*time + (1-gate)*text
//   out   = fused @ out_w^T + out_b                    (M=16384, N=896, K=896)

#define M_TOT 16384
#define D_DIM 896
#define K1    1792

#define BM 128
#define BN 128
#define BK 32
#define THREADS 128
#define STAGES 3
#define AB_OFF (STAGES * 512)                 // uint4 entries: B region offset
#define SMEM_BYTES (2 * STAGES * 512 * 16)    // 48 KB -> 2 CTAs/SM

static __device__ __half g_tf_h[(size_t)M_TOT * D_DIM];
static __device__ __half g_xf_h[(size_t)M_TOT * D_DIM];
static __device__ __half g_gw_h[(size_t)D_DIM * K1];
static __device__ __half g_ow_h[(size_t)D_DIM * D_DIM];
static __device__ __half g_fused[(size_t)M_TOT * D_DIM];

// ---------------- small helpers ---------------------------------------------
__device__ __forceinline__ void ldm_x4(uint32_t* r, uint32_t addr) {
    asm volatile("ldmatrix.sync.aligned.m8n8.x4.shared.b16 {%0,%1,%2,%3}, [%4];"
                 : "=r"(r[0]), "=r"(r[1]), "=r"(r[2]), "=r"(r[3]) : "r"(addr));
}
__device__ __forceinline__ void mma_f16(float* c, const uint32_t* a, const uint32_t* b) {
    asm volatile(
        "mma.sync.aligned.m16n8k16.row.col.f32.f16.f16.f32 "
        "{%0,%1,%2,%3}, {%4,%5,%6,%7}, {%8,%9}, {%0,%1,%2,%3};"
        : "+f"(c[0]), "+f"(c[1]), "+f"(c[2]), "+f"(c[3])
        : "r"(a[0]), "r"(a[1]), "r"(a[2]), "r"(a[3]), "r"(b[0]), "r"(b[1]));
}

// ---------------- fused fp32 -> fp16 pre-convert (one launch) ----------------
#define N_ACT ((size_t)M_TOT * D_DIM)
#define N_GW  ((size_t)D_DIM * K1)
#define N_OW  ((size_t)D_DIM * D_DIM)
__global__ void k_f2h_all(const float* __restrict__ tf, const float* __restrict__ xf,
                          const float* __restrict__ gw, const float* __restrict__ ow) {
    const size_t tot = (2 * N_ACT + N_GW + N_OW) / 4;
    for (size_t g = blockIdx.x * blockDim.x + threadIdx.x; g < tot;
         g += (size_t)gridDim.x * blockDim.x) {
        const float* src; __half* dst; size_t i = g * 4;
        if (i < N_ACT) {
            src = tf + i; dst = g_tf_h + i;
        } else if (i < 2 * N_ACT) {
            src = xf + (i - N_ACT); dst = g_xf_h + (i - N_ACT);
        } else if (i < 2 * N_ACT + N_GW) {
            src = gw + (i - 2 * N_ACT); dst = g_gw_h + (i - 2 * N_ACT);
        } else {
            src = ow + (i - 2 * N_ACT - N_GW); dst = g_ow_h + (i - 2 * N_ACT - N_GW);
        }
        float4 v = *reinterpret_cast<const float4*>(src);
        __half2 hh[2] = {__floats2half2_rn(v.x, v.y), __floats2half2_rn(v.z, v.w)};
        *reinterpret_cast<uint2*>(dst) = *reinterpret_cast<const uint2*>(hh);
    }
}

// ---------------- staging: LDG.128 -> regs -> swizzled STS.128 ---------------
// Tile = 128 rows x 32 k (half) for A and B. 16B entries:
//   entry(slab,row) = slab*128 + (row ^ (slab*2)), slab = k8/8 in {0..3}
// 128 threads: row32 = tid>>2 (0..31), slab = tid&3; u<4 covers 128 rows.
__device__ __forceinline__ void ldg_pair(uint4 (&ra)[4], uint4 (&rb)[4],
                                         const __half* __restrict__ A, int ldA,
                                         int m0, int kA,
                                         const __half* __restrict__ B, int ldB,
                                         int n0, int kB, int row32, int slab) {
#pragma unroll
    for (int u = 0; u < 4; u++) {
        const int row = row32 + u * 32;
        ra[u] = *reinterpret_cast<const uint4*>(&A[(size_t)(m0 + row) * ldA + kA + slab * 8]);
        rb[u] = *reinterpret_cast<const uint4*>(&B[(size_t)(n0 + row) * ldB + kB + slab * 8]);
    }
}
__device__ __forceinline__ void sts_pair(uint4* sm, int stage, const uint4 (&ra)[4],
                                         const uint4 (&rb)[4], int row32, int slab) {
#pragma unroll
    for (int u = 0; u < 4; u++) {
        const int row = row32 + u * 32;
        const int e = stage * 512 + slab * 128 + (row ^ (slab * 2));
        sm[e] = ra[u];
        sm[AB_OFF + e] = rb[u];
    }
}

// ---------------- compute: warp tile 64x64, mi=4 x ni=8, m16n8k16 ------------
#define GEMM_COMPUTE(cur)                                                         \
    _Pragma("unroll")                                                             \
    for (int ks = 0; ks < 2; ks++) {                                              \
        uint32_t af[4][4], bf[8][2];                                              \
        _Pragma("unroll")                                                         \
        for (int mi = 0; mi < 4; mi++) {                                          \
            const int slab = ks * 2 + a_kh;                                       \
            const int row = wm * 64 + mi * 16 + a_row;                            \
            ldm_x4(af[mi], sbase +                                                \
                   (uint32_t)((cur) * 512 + slab * 128 + (row ^ (slab * 2))) * 16); \
        }                                                                         \
        _Pragma("unroll")                                                         \
        for (int np = 0; np < 4; np++) {                                          \
            const int slab = ks * 2 + b_kh;                                       \
            const int nrow = wn * 64 + np * 16 + b_row;                           \
            uint32_t t[4];                                                        \
            ldm_x4(t, sbase + (uint32_t)AB_OFF * 16 +                             \
                   (uint32_t)((cur) * 512 + slab * 128 + (nrow ^ (slab * 2))) * 16); \
            bf[np * 2][0] = t[0]; bf[np * 2][1] = t[1];                           \
            bf[np * 2 + 1][0] = t[2]; bf[np * 2 + 1][1] = t[3];                   \
        }                                                                         \
        _Pragma("unroll")                                                         \
        for (int mi = 0; mi < 4; mi++)                                            \
            _Pragma("unroll")                                                     \
            for (int ni = 0; ni < 8; ni++)                                        \
                mma_f16(acc[mi][ni], af[mi], bf[ni]);                             \
    }

#define GEMM_PREAMBLE                                                             \
    extern __shared__ uint4 smem_dyn[];                                           \
    const uint32_t sbase = (uint32_t)__cvta_generic_to_shared(smem_dyn);          \
    const int tid  = threadIdx.x;                                                 \
    const int wid  = tid >> 5;                                                    \
    const int lane = tid & 31;                                                    \
    const int qrow = lane >> 2;                                                   \
    const int qk   = lane & 3;                                                    \
    const int wm   = wid & 1;                                                     \
    const int wn   = wid >> 1;                                                    \
    const int m0   = blockIdx.y * BM;                                             \
    const int n0   = blockIdx.x * BN;                                             \
    const int row32 = tid >> 2;                                                   \
    const int slabL = tid & 3;                                                    \
    const int a_row = lane & 15;                                                  \
    const int a_kh  = lane >> 4;                                                  \
    const int b_row = (lane & 7) + ((lane >> 4) << 3);                            \
    const int b_kh  = (lane >> 3) & 1;                                            \
    float acc[4][8][4];                                                           \
    _Pragma("unroll")                                                             \
    for (int mi = 0; mi < 4; mi++)                                                \
        _Pragma("unroll")                                                         \
        for (int ni = 0; ni < 8; ni++)                                            \
            _Pragma("unroll")                                                     \
            for (int t = 0; t < 4; t++) acc[mi][ni][t] = 0.f;

// R7 pipeline: 3-stage, one sync per tile.
//   iter kt: LDG(kt+2) -> compute(kt, slot kt%3) -> STS(kt+2 into (kt+2)%3 ==
//   (kt-1)%3, whose compute finished before the previous sync) -> sync.
#define GEMM_MAINLOOP(NT, SRC_A, LD_A, K_A, SRC_B, LD_B)                          \
    {                                                                             \
        uint4 ra[4], rb[4];                                                       \
        ldg_pair(ra, rb, SRC_A(0), LD_A, m0, K_A(0), SRC_B, LD_B, n0, 0, row32, slabL); \
        sts_pair(smem_dyn, 0, ra, rb, row32, slabL);                              \
        ldg_pair(ra, rb, SRC_A(BK), LD_A, m0, K_A(BK), SRC_B, LD_B, n0, BK, row32, slabL); \
        sts_pair(smem_dyn, 1, ra, rb, row32, slabL);                              \
        __syncthreads();                                                          \
        for (int kt = 0; kt < (NT); kt++) {                                       \
            const int kn = kt + 2;                                                \
            if (kn < (NT)) {                                                      \
                const int kb = kn * BK;                                           \
                ldg_pair(ra, rb, SRC_A(kb), LD_A, m0, K_A(kb), SRC_B, LD_B, n0, kb, row32, slabL); \
            }                                                                     \
            GEMM_COMPUTE(kt % STAGES)                                             \
            if (kn < (NT)) sts_pair(smem_dyn, kn % STAGES, ra, rb, row32, slabL); \
            __syncthreads();                                                      \
        }                                                                         \
    }

// ============================================================================
// Kernel 1: gate GEMM (K=1792, A = [time|text] concat) + sigmoid/blend fuse
// ============================================================================
#define GATE_SRC(kb) ((kb) < D_DIM ? g_tf_h : g_xf_h)
#define GATE_K(kb)   ((kb) < D_DIM ? (kb) : (kb) - D_DIM)
#define ID_SRC(kb)   (g_fused)
#define ID_K(kb)     (kb)

__global__ void __launch_bounds__(THREADS, 2)
k_gate_fuse(const float* __restrict__ gb)
{
    GEMM_PREAMBLE
    GEMM_MAINLOOP(K1 / BK, GATE_SRC, D_DIM, GATE_K, g_gw_h, K1)

    // epilogue: z = acc + gb; g = sigmoid(z); fused = g*tf + (1-g)*xf
    // blend inputs read from the HALF activation copies (halves DRAM traffic;
    // R6 established rel_err ~3.8e-4 for this substitution).
#pragma unroll
    for (int mi = 0; mi < 4; mi++) {
#pragma unroll
        for (int half = 0; half < 2; half++) {
            const int m = m0 + wm * 64 + mi * 16 + qrow + half * 8;
            const __half* trow = g_tf_h + (size_t)m * D_DIM;
            const __half* xrow = g_xf_h + (size_t)m * D_DIM;
            __half* frow = g_fused + (size_t)m * D_DIM;
#pragma unroll
            for (int ni = 0; ni < 8; ni++) {
                const int n = n0 + wn * 64 + ni * 8 + 2 * qk;
                const float c0 = acc[mi][ni][half * 2 + 0];
                const float c1 = acc[mi][ni][half * 2 + 1];
                const float2 gbv = *reinterpret_cast<const float2*>(&gb[n]);
                const float2 tv = __half22float2(*reinterpret_cast<const __half2*>(&trow[n]));
                const float2 xv = __half22float2(*reinterpret_cast<const __half2*>(&xrow[n]));
                const float g0 = 1.f / (1.f + __expf(-(c0 + gbv.x)));
                const float g1 = 1.f / (1.f + __expf(-(c1 + gbv.y)));
                const float f0 = g0 * tv.x + (1.f - g0) * xv.x;
                const float f1 = g1 * tv.y + (1.f - g1) * xv.y;
                *reinterpret_cast<__half2*>(&frow[n]) = __floats2half2_rn(f0, f1);
            }
        }
    }
}

// ============================================================================
// Kernel 2: out = fused @ out_w^T + out_b   (K=896)
// ============================================================================
__global__ void __launch_bounds__(THREADS, 2)
k_out_proj(const float* __restrict__ ob, float* __restrict__ out)
{
    GEMM_PREAMBLE
    GEMM_MAINLOOP(D_DIM / BK, ID_SRC, D_DIM, ID_K, g_ow_h, D_DIM)

#pragma unroll
    for (int mi = 0; mi < 4; mi++) {
#pragma unroll
        for (int half = 0; half < 2; half++) {
            const int m = m0 + wm * 64 + mi * 16 + qrow + half * 8;
            float* orow = out + (size_t)m * D_DIM;
#pragma unroll
            for (int ni = 0; ni < 8; ni++) {
                const int n = n0 + wn * 64 + ni * 8 + 2 * qk;
                const float2 obv = *reinterpret_cast<const float2*>(&ob[n]);
                float2 o;
                o.x = acc[mi][ni][half * 2 + 0] + obv.x;
                o.y = acc[mi][ni][half * 2 + 1] + obv.y;
                *reinterpret_cast<float2*>(&orow[n]) = o;
            }
        }
    }
}

extern "C" void kernel_launch(void* const* d_in, const int* in_sizes, int n_in,
                              void* d_out, int out_size) {
    const float* tf = (const float*)d_in[0];   // time_feat [16,1024,896]
    const float* xf = (const float*)d_in[1];   // text_feat [16,1024,896]
    // d_in[2] = word (dead: softmax over singleton axis == 1)
    const float* gw = (const float*)d_in[3];   // gate_w [896, 1792]
    const float* gb = (const float*)d_in[4];   // gate_b [896]
    const float* ow = (const float*)d_in[5];   // out_w  [896, 896]
    const float* ob = (const float*)d_in[6];   // out_b  [896]
    float* out = (float*)d_out;                // [16,1024,896] fp32

    static bool attr_set = false;
    if (!attr_set) {
        cudaFuncSetAttribute(k_gate_fuse, cudaFuncAttributeMaxDynamicSharedMemorySize, SMEM_BYTES);
        cudaFuncSetAttribute(k_out_proj, cudaFuncAttributeMaxDynamicSharedMemorySize, SMEM_BYTES);
        attr_set = true;
    }

    k_f2h_all<<<2368, 256>>>(tf, xf, gw, ow);

    dim3 grid(D_DIM / BN, M_TOT / BM);  // (7, 128)
    k_gate_fuse<<<grid, THREADS, SMEM_BYTES>>>(gb);
    k_out_proj<<<grid, THREADS, SMEM_BYTES>>>(ob, out);
}